// round 16
// baseline (speedup 1.0000x reference)
#include <cuda_runtime.h>
#include <cuda_fp16.h>
#include <cstdint>
#include <cstddef>

// ============================================================================
// QUIK quantized linear, B = in = out = 4096.
//   x_q = trunc(clip((x - min(x))/((max-min)/8) - 4, -4, 3))   (global affine)
//   w_q likewise; out[i,j] = (x_q[i,:]·w_q[j,:] + bias[j])*s_a*s_w
//                            + (zero_a + 4*s_a)*rowsum_w[i]    (note index i)
// R16: work-balanced job list. 296 CTAs x 3 full tiles + last 136 tiles split
// into 2 half-K jobs (272) -> critical path 3.5 tile-equivalents vs 4.0.
// Half-job partials (exact integer f32 sums) to scratch; combine kernel fuses.
// Pipeline: 2-stage x2-unrolled (handles runtime niter 64/32, both even).
// ============================================================================

#define DIM 4096
#define BM 128
#define BN 128
#define BK 64             // f16 elements per k-tile = 128 bytes per row
#define GRID_PERSIST 296  // 2 CTAs x 148 SMs
#define FULLJOBS 888      // tiles 0..887 as whole-K jobs
#define NHALF 136         // tiles 888..1023 split in two K halves
#define NJOBS (FULLJOBS + 2 * NHALF)       // 1160
#define STAGE_BYTES (2 * BM * 128)         // A(16K) + B(16K) = 32768
#define SMEM_TOTAL (2 * STAGE_BYTES)       // 65536

// ---------------- device scratch (allocation-free rule) ---------------------
__device__ unsigned g_xmin_e = 0xFFFFFFFFu, g_xmax_e = 0u;
__device__ unsigned g_wmin_e = 0xFFFFFFFFu, g_wmax_e = 0u;
__device__ float g_rowsum[DIM];
__device__ float g_consts[8];  // 0:s=sa*sw 1:shiftc 2:x_zero 3:x_scale 4:w_zero 5:w_scale
__device__ unsigned short g_xqh[(size_t)DIM * DIM];  // f16 bits of quantized x
__device__ unsigned short g_wqh[(size_t)DIM * DIM];  // f16 bits of quantized w
__device__ float g_partial[(size_t)2 * NHALF * BM * BN];  // 17.8MB half-K partials

// ---------------- PTX helpers (plain-sm80/75 features only) -----------------
__device__ __forceinline__ uint32_t smem_to_u32(const void* p) {
    uint32_t a;
    asm("{ .reg .u64 t; cvta.to.shared.u64 t, %1; cvt.u32.u64 %0, t; }" : "=r"(a) : "l"(p));
    return a;
}

#define CP_ASYNC16(saddr, gptr)                                              \
    asm volatile("cp.async.cg.shared.global [%0], [%1], 16;"                 \
                 :: "r"(saddr), "l"(gptr) : "memory")
#define CP_COMMIT() asm volatile("cp.async.commit_group;" ::: "memory")
#define CP_WAIT0()  asm volatile("cp.async.wait_group 0;" ::: "memory")

#define LDSM_X4(r, addr)                                                     \
    asm volatile("ldmatrix.sync.aligned.m8n8.x4.shared.b16 {%0,%1,%2,%3}, [%4];" \
                 : "=r"((r)[0]), "=r"((r)[1]), "=r"((r)[2]), "=r"((r)[3])    \
                 : "r"(addr))

// f16 HMMA, f32 accumulate: D(16x8) += A(16x16) * B(16x8)
#define MMA_F16(c, a, b0v, b1v)                                              \
    asm volatile("mma.sync.aligned.m16n8k16.row.col.f32.f16.f16.f32 "        \
                 "{%0,%1,%2,%3}, {%4,%5,%6,%7}, {%8,%9}, {%0,%1,%2,%3};"     \
                 : "+f"((c)[0]), "+f"((c)[1]), "+f"((c)[2]), "+f"((c)[3])    \
                 : "r"((a)[0]), "r"((a)[1]), "r"((a)[2]), "r"((a)[3]),       \
                   "r"(b0v), "r"(b1v))

// Monotone float<->uint encoding for atomic min/max on fp32
__device__ __forceinline__ unsigned fenc(float f) {
    unsigned u = __float_as_uint(f);
    return (u & 0x80000000u) ? ~u : (u | 0x80000000u);
}
__device__ __forceinline__ float fdec(unsigned e) {
    return (e & 0x80000000u) ? __uint_as_float(e & 0x7FFFFFFFu) : __uint_as_float(~e);
}

// ============================================================================
// Launch 1: per-row pass — global min/max of x and w, weight row sums
// ============================================================================
__global__ void __launch_bounds__(256) reduce_kernel(const float* __restrict__ x,
                                                     const float* __restrict__ w) {
    const int row = blockIdx.x, tid = threadIdx.x;
    const float4* xr = reinterpret_cast<const float4*>(x + ((size_t)row << 12));
    const float4* wr = reinterpret_cast<const float4*>(w + ((size_t)row << 12));
    float xmn = 3.4e38f, xmx = -3.4e38f, wmn = 3.4e38f, wmx = -3.4e38f, ws = 0.0f;
    for (int i = tid; i < 1024; i += 256) {
        float4 a = xr[i];
        xmn = fminf(xmn, fminf(fminf(a.x, a.y), fminf(a.z, a.w)));
        xmx = fmaxf(xmx, fmaxf(fmaxf(a.x, a.y), fmaxf(a.z, a.w)));
        float4 b = wr[i];
        wmn = fminf(wmn, fminf(fminf(b.x, b.y), fminf(b.z, b.w)));
        wmx = fmaxf(wmx, fmaxf(fmaxf(b.x, b.y), fmaxf(b.z, b.w)));
        ws += (b.x + b.y) + (b.z + b.w);
    }
    #pragma unroll
    for (int o = 16; o; o >>= 1) {
        xmn = fminf(xmn, __shfl_xor_sync(0xFFFFFFFFu, xmn, o));
        xmx = fmaxf(xmx, __shfl_xor_sync(0xFFFFFFFFu, xmx, o));
        wmn = fminf(wmn, __shfl_xor_sync(0xFFFFFFFFu, wmn, o));
        wmx = fmaxf(wmx, __shfl_xor_sync(0xFFFFFFFFu, wmx, o));
        ws += __shfl_xor_sync(0xFFFFFFFFu, ws, o);
    }
    __shared__ float s_xmn[8], s_xmx[8], s_wmn[8], s_wmx[8], s_ws[8];
    const int wid = tid >> 5, lane = tid & 31;
    if (lane == 0) { s_xmn[wid] = xmn; s_xmx[wid] = xmx; s_wmn[wid] = wmn; s_wmx[wid] = wmx; s_ws[wid] = ws; }
    __syncthreads();
    if (tid == 0) {
        float a = s_xmn[0], b = s_xmx[0], c = s_wmn[0], d = s_wmx[0], e = s_ws[0];
        #pragma unroll
        for (int i = 1; i < 8; i++) {
            a = fminf(a, s_xmn[i]); b = fmaxf(b, s_xmx[i]);
            c = fminf(c, s_wmn[i]); d = fmaxf(d, s_wmx[i]);
            e += s_ws[i];
        }
        atomicMin(&g_xmin_e, fenc(a)); atomicMax(&g_xmax_e, fenc(b));
        atomicMin(&g_wmin_e, fenc(c)); atomicMax(&g_wmax_e, fenc(d));
        g_rowsum[row] = e;
    }
}

// ============================================================================
// Launch 2: scalar constants
// ============================================================================
__global__ void finalize_kernel() {
    if (threadIdx.x == 0) {
        float xmin = fdec(g_xmin_e), xmax = fdec(g_xmax_e);
        float wmin = fdec(g_wmin_e), wmax = fdec(g_wmax_e);
        float sa = (xmax - xmin) * 0.125f;  // /8 exact
        float sw = (wmax - wmin) * 0.125f;
        g_consts[0] = sa * sw;
        g_consts[1] = xmin + 4.0f * sa;
        g_consts[2] = xmin; g_consts[3] = sa;
        g_consts[4] = wmin; g_consts[5] = sw;
    }
}

// ============================================================================
// Launch 3: quantize BOTH matrices to f16 scratch (blockIdx.y: 0=x, 1=w).
// ============================================================================
__global__ void __launch_bounds__(256) quant_kernel(const float* __restrict__ x,
                                                    const float* __restrict__ w) {
    const int which = blockIdx.y;
    const float zero  = which ? g_consts[4] : g_consts[2];
    const float scale = which ? g_consts[5] : g_consts[3];
    const float* src = which ? w : x;
    unsigned short* dst = which ? g_wqh : g_xqh;
    const size_t i = ((size_t)blockIdx.x * 256 + threadIdx.x) * 8;
    const float4* s4 = reinterpret_cast<const float4*>(src + i);
    float4 a = s4[0], b = s4[1];
    float v[8] = {a.x, a.y, a.z, a.w, b.x, b.y, b.z, b.w};
    unsigned r[4];
    #pragma unroll
    for (int k = 0; k < 4; k++) {
        float q0 = fminf(fmaxf(__fdiv_rn(v[2 * k] - zero, scale) - 4.0f, -4.0f), 3.0f);
        float q1 = fminf(fmaxf(__fdiv_rn(v[2 * k + 1] - zero, scale) - 4.0f, -4.0f), 3.0f);
        unsigned lo = __half_as_ushort(__float2half_rn((float)(int)q0));
        unsigned hi = __half_as_ushort(__float2half_rn((float)(int)q1));
        r[k] = lo | (hi << 16);
    }
    *reinterpret_cast<uint4*>(dst + i) = make_uint4(r[0], r[1], r[2], r[3]);
}

// ============================================================================
// Launch 4 (ncu-captured slot): persistent f16 HMMA GEMM, f32 accumulate.
// Balanced job list: jobs 0..887 full tiles; jobs 888..1159 = half-K jobs of
// tiles 888..1023 (partials to g_partial). 2-stage x2-unrolled cp.async
// pipeline, register fragment double-buffering, warp tile 64x64 (2x2 warps).
// ============================================================================
__global__ void __launch_bounds__(128, 2) gemm_kernel(const float* __restrict__ bias,
                                                      float* __restrict__ out) {
    extern __shared__ char smem[];
    const int tid = threadIdx.x, lane = tid & 31, wid = tid >> 5;
    const int warp_m = wid >> 1, warp_n = wid & 1;   // 2 x 2 warp grid
    const uint32_t sm0 = smem_to_u32(smem);

    // copy-loop: 2048 16B-chunks per stage; 16 per thread
    const int cp_rc = tid >> 3;            // 0..15
    const int cp_c  = tid & 7;
    const uint32_t cp_sbase = (uint32_t)(cp_rc * 128 + ((cp_c ^ (cp_rc & 7)) << 4));
    const uint32_t cp_gbase = ((uint32_t)cp_rc << 13) + ((uint32_t)cp_c << 4);

    const int a_row  = warp_m * 64 + (lane & 7) + ((lane >> 3) & 1) * 8;
    const int a_kbit = (lane >> 4) & 1;
    const int a_xor  = a_row & 7;
    uint32_t a_rowoff[4];
    #pragma unroll
    for (int mb = 0; mb < 4; mb++) a_rowoff[mb] = (uint32_t)(a_row + mb * 16) * 128;

    const int b_col  = warp_n * 64 + (lane & 7) + ((lane >> 3) & 1) * 8;
    const int b_kbit = (lane >> 4) & 1;
    const int b_xor  = b_col & 7;
    uint32_t b_rowoff[4];
    #pragma unroll
    for (int h = 0; h < 4; h++) b_rowoff[h] = (uint32_t)(b_col + h * 16) * 128;

    uint32_t ac_k[4], bc_k[4];
    #pragma unroll
    for (int ks = 0; ks < 4; ks++) {
        ac_k[ks] = (uint32_t)(((2 * ks + a_kbit) ^ a_xor) << 4);
        bc_k[ks] = (uint32_t)(((2 * ks + b_kbit) ^ b_xor) << 4);
    }

    const float s = g_consts[0], shc = g_consts[1];

    uint32_t Af[2][4][4], Bff[2][4][4];  // double-buffered fragments

    #pragma unroll 1
    for (int job = blockIdx.x; job < NJOBS; job += GRID_PERSIST) {
        int tile, kbase, niter;
        if (job < FULLJOBS) { tile = job; kbase = 0; niter = 64; }
        else { int idx = job - FULLJOBS; tile = FULLJOBS + (idx >> 1); kbase = (idx & 1) * 32; niter = 32; }
        const int by = tile >> 5, bx = tile & 31;
        const unsigned short* Agbase = g_xqh + ((size_t)(by * BM) << 12) + (size_t)kbase * BK;
        const unsigned short* Bgbase = g_wqh + ((size_t)(bx * BN) << 12) + (size_t)kbase * BK;

        float acc[4][8][4];
        #pragma unroll
        for (int mb = 0; mb < 4; mb++)
            #pragma unroll
            for (int nb = 0; nb < 8; nb++)
                #pragma unroll
                for (int e = 0; e < 4; e++) acc[mb][nb][e] = 0.0f;

        auto load_stage = [&](int kt, uint32_t As) {
            const uint32_t Bs = As + BM * 128;
            const char* Ag = reinterpret_cast<const char*>(Agbase + (size_t)kt * BK) + cp_gbase;
            const char* Bg = reinterpret_cast<const char*>(Bgbase + (size_t)kt * BK) + cp_gbase;
            #pragma unroll
            for (int i = 0; i < 8; i++) {
                CP_ASYNC16(As + cp_sbase + i * 2048, Ag + i * (size_t)131072);
                CP_ASYNC16(Bs + cp_sbase + i * 2048, Bg + i * (size_t)131072);
            }
        };
        auto ldsm_frags = [&](int buf, uint32_t As, int ks) {
            const uint32_t Bs = As + BM * 128;
            #pragma unroll
            for (int mb = 0; mb < 4; mb++) LDSM_X4(Af[buf][mb],  As + a_rowoff[mb] + ac_k[ks]);
            #pragma unroll
            for (int h = 0; h < 4; h++)    LDSM_X4(Bff[buf][h],  Bs + b_rowoff[h] + bc_k[ks]);
        };
        auto mma_block = [&](int buf) {
            #pragma unroll
            for (int mb = 0; mb < 4; mb++)
                #pragma unroll
                for (int h = 0; h < 4; h++) {
                    MMA_F16(acc[mb][2 * h],     Af[buf][mb], Bff[buf][h][0], Bff[buf][h][2]);
                    MMA_F16(acc[mb][2 * h + 1], Af[buf][mb], Bff[buf][h][1], Bff[buf][h][3]);
                }
        };
        // One kt iteration, 2-stage pipeline. Barrier (after last read of As)
        // is preceded by CP_WAIT0 (group kt+1 resident); load kt+2 into As is
        // issued AFTER the barrier (all warps done reading As).
        auto iteration = [&](int kt, uint32_t As, uint32_t Asn) {
            ldsm_frags(1, As, 1);
            mma_block(0);
            ldsm_frags(0, As, 2);
            mma_block(1);
            ldsm_frags(1, As, 3);          // last read of current stage
            if (kt + 1 < niter) {
                CP_WAIT0();                 // group kt+1 complete (issued 1 kt ago)
                __syncthreads();            // all warps done reading As
                if (kt + 2 < niter) load_stage(kt + 2, As);
                CP_COMMIT();
                mma_block(0);               // ks=2
                ldsm_frags(0, Asn, 0);      // ks=0 of next kt (from Asn)
                mma_block(1);               // ks=3
            } else {
                mma_block(0);
                mma_block(1);
            }
        };

        const uint32_t S0 = sm0, S1 = sm0 + STAGE_BYTES;
        load_stage(0, S0); CP_COMMIT();
        load_stage(1, S1); CP_COMMIT();
        CP_WAIT0();
        __syncthreads();
        ldsm_frags(0, S0, 0);

        #pragma unroll 1
        for (int i2 = 0; i2 < niter / 2; i2++) {
            iteration(2 * i2,     S0, S1);
            iteration(2 * i2 + 1, S1, S0);
        }

        // Epilogue
        if (job < FULLJOBS) {
            const int gr0 = by * BM + warp_m * 64 + (lane >> 2);
            const int gc0 = bx * BN + warp_n * 64 + (lane & 3) * 2;
            #pragma unroll
            for (int mb = 0; mb < 4; mb++) {
                const int r0 = gr0 + mb * 16, r1 = r0 + 8;
                const float sh0 = shc * g_rowsum[r0];
                const float sh1 = shc * g_rowsum[r1];
                float* o0 = out + ((size_t)r0 << 12);
                float* o1 = out + ((size_t)r1 << 12);
                #pragma unroll
                for (int nb = 0; nb < 8; nb++) {
                    const int gc = gc0 + nb * 8;
                    const float bv0 = bias[gc], bv1 = bias[gc + 1];
                    float2 v0, v1;
                    v0.x = fmaf(acc[mb][nb][0] + bv0, s, sh0);
                    v0.y = fmaf(acc[mb][nb][1] + bv1, s, sh0);
                    v1.x = fmaf(acc[mb][nb][2] + bv0, s, sh1);
                    v1.y = fmaf(acc[mb][nb][3] + bv1, s, sh1);
                    *reinterpret_cast<float2*>(o0 + gc) = v0;
                    *reinterpret_cast<float2*>(o1 + gc) = v1;
                }
            }
        } else {
            // raw partial (exact integer sums) to scratch, local tile coords
            float* pt = g_partial + (size_t)(job - FULLJOBS) * (BM * BN);
            const int lr0 = warp_m * 64 + (lane >> 2);
            const int lc0 = warp_n * 64 + (lane & 3) * 2;
            #pragma unroll
            for (int mb = 0; mb < 4; mb++) {
                const int r0 = lr0 + mb * 16, r1 = r0 + 8;
                #pragma unroll
                for (int nb = 0; nb < 8; nb++) {
                    const int lc = lc0 + nb * 8;
                    float2 v0, v1;
                    v0.x = acc[mb][nb][0]; v0.y = acc[mb][nb][1];
                    v1.x = acc[mb][nb][2]; v1.y = acc[mb][nb][3];
                    *reinterpret_cast<float2*>(pt + r0 * BN + lc) = v0;
                    *reinterpret_cast<float2*>(pt + r1 * BN + lc) = v1;
                }
            }
        }
        __syncthreads();  // all warps done before next job's loads
    }

    // Reset min/max accumulators for the next kernel_launch call
    if (blockIdx.x == 0 && tid == 0) {
        g_xmin_e = 0xFFFFFFFFu; g_xmax_e = 0u;
        g_wmin_e = 0xFFFFFFFFu; g_wmax_e = 0u;
    }
}

// ============================================================================
// Launch 5: combine half-K partials for tiles 888..1023.
// out = (p0 + p1 + bias)*s + shc*rowsum.  2.23M elements, 8 per thread.
// ============================================================================
__global__ void __launch_bounds__(256) combine_kernel(const float* __restrict__ bias,
                                                      float* __restrict__ out) {
    const size_t e = ((size_t)blockIdx.x * 256 + threadIdx.x) * 8;  // element base
    const int ti  = (int)(e >> 14);          // half-tile index 0..135
    const int off = (int)(e & 16383);
    const int r = off >> 7, c = off & 127;
    const int tile = FULLJOBS + ti;
    const int row = (tile >> 5) * BM + r;
    const int col = (tile & 31) * BN + c;
    const float s = g_consts[0];
    const float sh = g_consts[1] * g_rowsum[row];
    const float* p0 = g_partial + (size_t)(2 * ti) * (BM * BN) + off;
    const float* p1 = p0 + (BM * BN);
    float* o = out + ((size_t)row << 12) + col;
    const float* bv = bias + col;
    #pragma unroll
    for (int k = 0; k < 2; k++) {
        float4 a = reinterpret_cast<const float4*>(p0)[k];
        float4 b = reinterpret_cast<const float4*>(p1)[k];
        float4 bb = reinterpret_cast<const float4*>(bv)[k];
        float4 v;
        v.x = fmaf(a.x + b.x + bb.x, s, sh);
        v.y = fmaf(a.y + b.y + bb.y, s, sh);
        v.z = fmaf(a.z + b.z + bb.z, s, sh);
        v.w = fmaf(a.w + b.w + bb.w, s, sh);
        reinterpret_cast<float4*>(o)[k] = v;
    }
}

// ============================================================================
extern "C" void kernel_launch(void* const* d_in, const int* in_sizes, int n_in,
                              void* d_out, int out_size) {
    (void)in_sizes; (void)n_in; (void)out_size;
    const float* x    = (const float*)d_in[0];
    const float* w    = (const float*)d_in[1];
    const float* bias = (const float*)d_in[2];
    float* out = (float*)d_out;

    reduce_kernel<<<DIM, 256>>>(x, w);                            // launch 1
    finalize_kernel<<<1, 32>>>();                                 // launch 2
    quant_kernel<<<dim3(DIM * DIM / (8 * 256), 2), 256>>>(x, w);  // launch 3
    cudaFuncSetAttribute(gemm_kernel, cudaFuncAttributeMaxDynamicSharedMemorySize, SMEM_TOTAL);
    gemm_kernel<<<GRID_PERSIST, 128, SMEM_TOTAL>>>(bias, out);    // launch 4
    combine_kernel<<<(NHALF * BM * BN) / (256 * 8), 256>>>(bias, out);  // launch 5
}

// round 17
// speedup vs baseline: 1.0406x; 1.0406x over previous
#include <cuda_runtime.h>
#include <cuda_fp16.h>
#include <cstdint>
#include <cstddef>

// ============================================================================
// QUIK quantized linear, B = in = out = 4096.
//   x_q = trunc(clip((x - min(x))/((max-min)/8) - 4, -4, 3))   (global affine)
//   w_q likewise; out[i,j] = (x_q[i,:]·w_q[j,:] + bias[j])*s_a*s_w
//                            + (zero_a + 4*s_a)*rowsum_w[i]    (note index i)
// R17: R15's proven 3-stage/unroll-3 mainloop (81% tensor) + work-balanced
// job list (888 full + 272 half-K jobs -> critical path 3.5 vs 4.0 tiles).
// Half-K partials combined IN-KERNEL via serial split-K (ticket atomics):
// no combine launch, half the scratch traffic of R16. Cross-partial f32 add
// of exact integers is commutative -> bit-deterministic.
// ============================================================================

#define DIM 4096
#define BM 128
#define BN 128
#define BK 64             // f16 elements per k-tile = 128 bytes per row
#define GRID_PERSIST 296  // 2 CTAs x 148 SMs
#define FULLJOBS 888      // tiles 0..887 as whole-K jobs
#define NHALF 136         // tiles 888..1023 split in two K halves
#define NJOBS (FULLJOBS + 2 * NHALF)       // 1160
#define STAGE_BYTES (2 * BM * 128)         // A(16K) + B(16K) = 32768
#define SMEM_TOTAL (3 * STAGE_BYTES)       // 98304 (3-stage)

// ---------------- device scratch (allocation-free rule) ---------------------
__device__ unsigned g_xmin_e = 0xFFFFFFFFu, g_xmax_e = 0u;
__device__ unsigned g_wmin_e = 0xFFFFFFFFu, g_wmax_e = 0u;
__device__ float g_rowsum[DIM];
__device__ float g_consts[8];  // 0:s=sa*sw 1:shiftc 2:x_zero 3:x_scale 4:w_zero 5:w_scale
__device__ unsigned short g_xqh[(size_t)DIM * DIM];  // f16 bits of quantized x
__device__ unsigned short g_wqh[(size_t)DIM * DIM];  // f16 bits of quantized w
__device__ float g_partial[(size_t)2 * NHALF * BM * BN];  // half-K partials
__device__ unsigned g_cnt[NHALF];  // per-tile tickets (zero-init; reset in-kernel)

// ---------------- PTX helpers (plain-sm80/75 features only) -----------------
__device__ __forceinline__ uint32_t smem_to_u32(const void* p) {
    uint32_t a;
    asm("{ .reg .u64 t; cvta.to.shared.u64 t, %1; cvt.u32.u64 %0, t; }" : "=r"(a) : "l"(p));
    return a;
}

#define CP_ASYNC16(saddr, gptr)                                              \
    asm volatile("cp.async.cg.shared.global [%0], [%1], 16;"                 \
                 :: "r"(saddr), "l"(gptr) : "memory")
#define CP_COMMIT() asm volatile("cp.async.commit_group;" ::: "memory")
#define CP_WAIT1()  asm volatile("cp.async.wait_group 1;" ::: "memory")
#define CP_WAIT0()  asm volatile("cp.async.wait_group 0;" ::: "memory")

#define LDSM_X4(r, addr)                                                     \
    asm volatile("ldmatrix.sync.aligned.m8n8.x4.shared.b16 {%0,%1,%2,%3}, [%4];" \
                 : "=r"((r)[0]), "=r"((r)[1]), "=r"((r)[2]), "=r"((r)[3])    \
                 : "r"(addr))

// f16 HMMA, f32 accumulate: D(16x8) += A(16x16) * B(16x8)
#define MMA_F16(c, a, b0v, b1v)                                              \
    asm volatile("mma.sync.aligned.m16n8k16.row.col.f32.f16.f16.f32 "        \
                 "{%0,%1,%2,%3}, {%4,%5,%6,%7}, {%8,%9}, {%0,%1,%2,%3};"     \
                 : "+f"((c)[0]), "+f"((c)[1]), "+f"((c)[2]), "+f"((c)[3])    \
                 : "r"((a)[0]), "r"((a)[1]), "r"((a)[2]), "r"((a)[3]),       \
                   "r"(b0v), "r"(b1v))

// Monotone float<->uint encoding for atomic min/max on fp32
__device__ __forceinline__ unsigned fenc(float f) {
    unsigned u = __float_as_uint(f);
    return (u & 0x80000000u) ? ~u : (u | 0x80000000u);
}
__device__ __forceinline__ float fdec(unsigned e) {
    return (e & 0x80000000u) ? __uint_as_float(e & 0x7FFFFFFFu) : __uint_as_float(~e);
}

// ============================================================================
// Launch 1: per-row pass — global min/max of x and w, weight row sums
// ============================================================================
__global__ void __launch_bounds__(256) reduce_kernel(const float* __restrict__ x,
                                                     const float* __restrict__ w) {
    const int row = blockIdx.x, tid = threadIdx.x;
    const float4* xr = reinterpret_cast<const float4*>(x + ((size_t)row << 12));
    const float4* wr = reinterpret_cast<const float4*>(w + ((size_t)row << 12));
    float xmn = 3.4e38f, xmx = -3.4e38f, wmn = 3.4e38f, wmx = -3.4e38f, ws = 0.0f;
    for (int i = tid; i < 1024; i += 256) {
        float4 a = xr[i];
        xmn = fminf(xmn, fminf(fminf(a.x, a.y), fminf(a.z, a.w)));
        xmx = fmaxf(xmx, fmaxf(fmaxf(a.x, a.y), fmaxf(a.z, a.w)));
        float4 b = wr[i];
        wmn = fminf(wmn, fminf(fminf(b.x, b.y), fminf(b.z, b.w)));
        wmx = fmaxf(wmx, fmaxf(fmaxf(b.x, b.y), fmaxf(b.z, b.w)));
        ws += (b.x + b.y) + (b.z + b.w);
    }
    #pragma unroll
    for (int o = 16; o; o >>= 1) {
        xmn = fminf(xmn, __shfl_xor_sync(0xFFFFFFFFu, xmn, o));
        xmx = fmaxf(xmx, __shfl_xor_sync(0xFFFFFFFFu, xmx, o));
        wmn = fminf(wmn, __shfl_xor_sync(0xFFFFFFFFu, wmn, o));
        wmx = fmaxf(wmx, __shfl_xor_sync(0xFFFFFFFFu, wmx, o));
        ws += __shfl_xor_sync(0xFFFFFFFFu, ws, o);
    }
    __shared__ float s_xmn[8], s_xmx[8], s_wmn[8], s_wmx[8], s_ws[8];
    const int wid = tid >> 5, lane = tid & 31;
    if (lane == 0) { s_xmn[wid] = xmn; s_xmx[wid] = xmx; s_wmn[wid] = wmn; s_wmx[wid] = wmx; s_ws[wid] = ws; }
    __syncthreads();
    if (tid == 0) {
        float a = s_xmn[0], b = s_xmx[0], c = s_wmn[0], d = s_wmx[0], e = s_ws[0];
        #pragma unroll
        for (int i = 1; i < 8; i++) {
            a = fminf(a, s_xmn[i]); b = fmaxf(b, s_xmx[i]);
            c = fminf(c, s_wmn[i]); d = fmaxf(d, s_wmx[i]);
            e += s_ws[i];
        }
        atomicMin(&g_xmin_e, fenc(a)); atomicMax(&g_xmax_e, fenc(b));
        atomicMin(&g_wmin_e, fenc(c)); atomicMax(&g_wmax_e, fenc(d));
        g_rowsum[row] = e;
    }
}

// ============================================================================
// Launch 2: scalar constants
// ============================================================================
__global__ void finalize_kernel() {
    if (threadIdx.x == 0) {
        float xmin = fdec(g_xmin_e), xmax = fdec(g_xmax_e);
        float wmin = fdec(g_wmin_e), wmax = fdec(g_wmax_e);
        float sa = (xmax - xmin) * 0.125f;  // /8 exact
        float sw = (wmax - wmin) * 0.125f;
        g_consts[0] = sa * sw;
        g_consts[1] = xmin + 4.0f * sa;
        g_consts[2] = xmin; g_consts[3] = sa;
        g_consts[4] = wmin; g_consts[5] = sw;
    }
}

// ============================================================================
// Launch 3: quantize BOTH matrices to f16 scratch (blockIdx.y: 0=x, 1=w).
// ============================================================================
__global__ void __launch_bounds__(256) quant_kernel(const float* __restrict__ x,
                                                    const float* __restrict__ w) {
    const int which = blockIdx.y;
    const float zero  = which ? g_consts[4] : g_consts[2];
    const float scale = which ? g_consts[5] : g_consts[3];
    const float* src = which ? w : x;
    unsigned short* dst = which ? g_wqh : g_xqh;
    const size_t i = ((size_t)blockIdx.x * 256 + threadIdx.x) * 8;
    const float4* s4 = reinterpret_cast<const float4*>(src + i);
    float4 a = s4[0], b = s4[1];
    float v[8] = {a.x, a.y, a.z, a.w, b.x, b.y, b.z, b.w};
    unsigned r[4];
    #pragma unroll
    for (int k = 0; k < 4; k++) {
        float q0 = fminf(fmaxf(__fdiv_rn(v[2 * k] - zero, scale) - 4.0f, -4.0f), 3.0f);
        float q1 = fminf(fmaxf(__fdiv_rn(v[2 * k + 1] - zero, scale) - 4.0f, -4.0f), 3.0f);
        unsigned lo = __half_as_ushort(__float2half_rn((float)(int)q0));
        unsigned hi = __half_as_ushort(__float2half_rn((float)(int)q1));
        r[k] = lo | (hi << 16);
    }
    *reinterpret_cast<uint4*>(dst + i) = make_uint4(r[0], r[1], r[2], r[3]);
}

// ============================================================================
// Launch 4 (ncu-captured slot): persistent f16 HMMA GEMM, f32 accumulate.
// R15 mainloop (3-stage cp.async, unroll-3 with compile-time stage addrs,
// fragment double-buffering, hoisted barrier) generalized to runtime niter
// (64 full / 32 half). Half-K jobs combine via serial split-K tickets.
// ============================================================================
__global__ void __launch_bounds__(128, 2) gemm_kernel(const float* __restrict__ bias,
                                                      float* __restrict__ out) {
    extern __shared__ char smem[];
    const int tid = threadIdx.x, lane = tid & 31, wid = tid >> 5;
    const int warp_m = wid >> 1, warp_n = wid & 1;   // 2 x 2 warp grid
    const uint32_t sm0 = smem_to_u32(smem);

    // copy-loop: 2048 16B-chunks per stage; 16 per thread
    const int cp_rc = tid >> 3;            // 0..15
    const int cp_c  = tid & 7;
    const uint32_t cp_sbase = (uint32_t)(cp_rc * 128 + ((cp_c ^ (cp_rc & 7)) << 4));
    const uint32_t cp_gbase = ((uint32_t)cp_rc << 13) + ((uint32_t)cp_c << 4);

    const int a_row  = warp_m * 64 + (lane & 7) + ((lane >> 3) & 1) * 8;
    const int a_kbit = (lane >> 4) & 1;
    const int a_xor  = a_row & 7;
    uint32_t a_rowoff[4];
    #pragma unroll
    for (int mb = 0; mb < 4; mb++) a_rowoff[mb] = (uint32_t)(a_row + mb * 16) * 128;

    const int b_col  = warp_n * 64 + (lane & 7) + ((lane >> 3) & 1) * 8;
    const int b_kbit = (lane >> 4) & 1;
    const int b_xor  = b_col & 7;
    uint32_t b_rowoff[4];
    #pragma unroll
    for (int h = 0; h < 4; h++) b_rowoff[h] = (uint32_t)(b_col + h * 16) * 128;

    uint32_t ac_k[4], bc_k[4];
    #pragma unroll
    for (int ks = 0; ks < 4; ks++) {
        ac_k[ks] = (uint32_t)(((2 * ks + a_kbit) ^ a_xor) << 4);
        bc_k[ks] = (uint32_t)(((2 * ks + b_kbit) ^ b_xor) << 4);
    }

    const float s = g_consts[0], shc = g_consts[1];

    uint32_t Af[2][4][4], Bff[2][4][4];  // double-buffered fragments

    #pragma unroll 1
    for (int job = blockIdx.x; job < NJOBS; job += GRID_PERSIST) {
        int tile, kbase, niter;
        if (job < FULLJOBS) { tile = job; kbase = 0; niter = 64; }
        else { int idx = job - FULLJOBS; tile = FULLJOBS + (idx >> 1); kbase = (idx & 1) * 32; niter = 32; }
        const int by = tile >> 5, bx = tile & 31;
        const unsigned short* Agbase = g_xqh + ((size_t)(by * BM) << 12) + (size_t)kbase * BK;
        const unsigned short* Bgbase = g_wqh + ((size_t)(bx * BN) << 12) + (size_t)kbase * BK;

        float acc[4][8][4];
        #pragma unroll
        for (int mb = 0; mb < 4; mb++)
            #pragma unroll
            for (int nb = 0; nb < 8; nb++)
                #pragma unroll
                for (int e = 0; e < 4; e++) acc[mb][nb][e] = 0.0f;

        auto load_stage = [&](int kt, uint32_t As) {
            const uint32_t Bs = As + BM * 128;
            const char* Ag = reinterpret_cast<const char*>(Agbase + (size_t)kt * BK) + cp_gbase;
            const char* Bg = reinterpret_cast<const char*>(Bgbase + (size_t)kt * BK) + cp_gbase;
            #pragma unroll
            for (int i = 0; i < 8; i++) {
                CP_ASYNC16(As + cp_sbase + i * 2048, Ag + i * (size_t)131072);
                CP_ASYNC16(Bs + cp_sbase + i * 2048, Bg + i * (size_t)131072);
            }
        };
        auto ldsm_frags = [&](int buf, uint32_t As, int ks) {
            const uint32_t Bs = As + BM * 128;
            #pragma unroll
            for (int mb = 0; mb < 4; mb++) LDSM_X4(Af[buf][mb],  As + a_rowoff[mb] + ac_k[ks]);
            #pragma unroll
            for (int h = 0; h < 4; h++)    LDSM_X4(Bff[buf][h],  Bs + b_rowoff[h] + bc_k[ks]);
        };
        auto mma_block = [&](int buf) {
            #pragma unroll
            for (int mb = 0; mb < 4; mb++)
                #pragma unroll
                for (int h = 0; h < 4; h++) {
                    MMA_F16(acc[mb][2 * h],     Af[buf][mb], Bff[buf][h][0], Bff[buf][h][2]);
                    MMA_F16(acc[mb][2 * h + 1], Af[buf][mb], Bff[buf][h][1], Bff[buf][h][3]);
                }
        };
        // One kt iteration, compile-time stage addresses (R15 structure).
        // Barrier after last read of current stage, before mma_block(2):
        // two MMA blocks (~512 tensor-cyc) absorb inter-warp skew.
        auto iteration = [&](int kt, uint32_t As, uint32_t Asn, uint32_t Asl) {
            if (kt + 2 < niter) load_stage(kt + 2, Asl);
            CP_COMMIT();
            ldsm_frags(1, As, 1);
            mma_block(0);
            ldsm_frags(0, As, 2);
            mma_block(1);
            ldsm_frags(1, As, 3);          // last read of current stage
            if (kt + 1 < niter) {
                CP_WAIT1();                 // next stage resident
                __syncthreads();            // stage (kt)%3 now safe to overwrite
                mma_block(0);               // ks=2
                ldsm_frags(0, Asn, 0);      // ks=0 of next kt
                mma_block(1);               // ks=3
            } else {
                mma_block(0);
                mma_block(1);
            }
        };

        const uint32_t S0 = sm0, S1 = sm0 + STAGE_BYTES, S2 = sm0 + 2 * STAGE_BYTES;
        load_stage(0, S0); CP_COMMIT();
        load_stage(1, S1); CP_COMMIT();
        CP_WAIT1();
        __syncthreads();
        ldsm_frags(0, S0, 0);

        // niter=64: 21 triples + 1 tail; niter=32: 10 triples + 2 tails.
        // Both 63 and 30 are divisible by 3 -> tails start at stage S0.
        const int full3 = (niter - 1) / 3;
        int kt = 0;
        #pragma unroll 1
        for (int t3 = 0; t3 < full3; t3++, kt += 3) {
            iteration(kt,     S0, S1, S2);
            iteration(kt + 1, S1, S2, S0);
            iteration(kt + 2, S2, S0, S1);
        }
        iteration(kt, S0, S1, S2);
        if (kt + 1 < niter) iteration(kt + 1, S1, S2, S0);

        CP_WAIT0();  // drain before smem reuse

        if (job < FULLJOBS) {
            // Fused epilogue: out[r][c] = (acc + bias[c]) * s + shc*rowsum[r]
            const int gr0 = by * BM + warp_m * 64 + (lane >> 2);
            const int gc0 = bx * BN + warp_n * 64 + (lane & 3) * 2;
            #pragma unroll
            for (int mb = 0; mb < 4; mb++) {
                const int r0 = gr0 + mb * 16, r1 = r0 + 8;
                const float sh0 = shc * g_rowsum[r0];
                const float sh1 = shc * g_rowsum[r1];
                float* o0 = out + ((size_t)r0 << 12);
                float* o1 = out + ((size_t)r1 << 12);
                #pragma unroll
                for (int nb = 0; nb < 8; nb++) {
                    const int gc = gc0 + nb * 8;
                    const float bv0 = bias[gc], bv1 = bias[gc + 1];
                    float2 v0, v1;
                    v0.x = fmaf(acc[mb][nb][0] + bv0, s, sh0);
                    v0.y = fmaf(acc[mb][nb][1] + bv1, s, sh0);
                    v1.x = fmaf(acc[mb][nb][2] + bv0, s, sh1);
                    v1.y = fmaf(acc[mb][nb][3] + bv1, s, sh1);
                    *reinterpret_cast<float2*>(o0 + gc) = v0;
                    *reinterpret_cast<float2*>(o1 + gc) = v1;
                }
            }
        } else {
            // Serial split-K: write my partial, take a ticket; the second
            // finisher reads the partner's partial and writes the final out.
            const int idx = job - FULLJOBS;
            const int ti  = idx >> 1;
            const int kh  = idx & 1;
            float* myp = g_partial + ((size_t)(2 * ti + kh)) * (BM * BN);
            const int lr0 = warp_m * 64 + (lane >> 2);
            const int lc0 = warp_n * 64 + (lane & 3) * 2;
            #pragma unroll
            for (int mb = 0; mb < 4; mb++) {
                const int r0 = lr0 + mb * 16, r1 = r0 + 8;
                #pragma unroll
                for (int nb = 0; nb < 8; nb++) {
                    const int lc = lc0 + nb * 8;
                    float2 v0, v1;
                    v0.x = acc[mb][nb][0]; v0.y = acc[mb][nb][1];
                    v1.x = acc[mb][nb][2]; v1.y = acc[mb][nb][3];
                    *reinterpret_cast<float2*>(myp + r0 * BN + lc) = v0;
                    *reinterpret_cast<float2*>(myp + r1 * BN + lc) = v1;
                }
            }
            __threadfence();     // my partial visible before my ticket
            __syncthreads();     // all warps' partials written+fenced
            if (tid == 0)
                *reinterpret_cast<volatile unsigned*>(smem) = atomicAdd(&g_cnt[ti], 1u);
            __syncthreads();
            const unsigned ord = *reinterpret_cast<volatile unsigned*>(smem);
            if (ord == 1u) {     // I'm second: partner's partial is visible
                __threadfence();
                const float* pp = g_partial + ((size_t)(2 * ti + (kh ^ 1))) * (BM * BN);
                const int gr0 = by * BM + lr0;
                const int gc0 = bx * BN + lc0;
                #pragma unroll
                for (int mb = 0; mb < 4; mb++) {
                    const int r0 = gr0 + mb * 16, r1 = r0 + 8;
                    const int pr0 = lr0 + mb * 16, pr1 = pr0 + 8;
                    const float sh0 = shc * g_rowsum[r0];
                    const float sh1 = shc * g_rowsum[r1];
                    float* o0 = out + ((size_t)r0 << 12);
                    float* o1 = out + ((size_t)r1 << 12);
                    #pragma unroll
                    for (int nb = 0; nb < 8; nb++) {
                        const int lc = lc0 + nb * 8;
                        const int gc = gc0 + nb * 8;
                        float2 q0 = *reinterpret_cast<const float2*>(pp + pr0 * BN + lc);
                        float2 q1 = *reinterpret_cast<const float2*>(pp + pr1 * BN + lc);
                        const float bv0 = bias[gc], bv1 = bias[gc + 1];
                        float2 v0, v1;
                        v0.x = fmaf(acc[mb][nb][0] + q0.x + bv0, s, sh0);
                        v0.y = fmaf(acc[mb][nb][1] + q0.y + bv1, s, sh0);
                        v1.x = fmaf(acc[mb][nb][2] + q1.x + bv0, s, sh1);
                        v1.y = fmaf(acc[mb][nb][3] + q1.y + bv1, s, sh1);
                        *reinterpret_cast<float2*>(o0 + gc) = v0;
                        *reinterpret_cast<float2*>(o1 + gc) = v1;
                    }
                }
                if (tid == 0) g_cnt[ti] = 0;   // re-arm for next launch
            }
        }
        __syncthreads();  // all warps done before next job's loads
    }

    // Reset min/max accumulators for the next kernel_launch call
    if (blockIdx.x == 0 && tid == 0) {
        g_xmin_e = 0xFFFFFFFFu; g_xmax_e = 0u;
        g_wmin_e = 0xFFFFFFFFu; g_wmax_e = 0u;
    }
}

// ============================================================================
extern "C" void kernel_launch(void* const* d_in, const int* in_sizes, int n_in,
                              void* d_out, int out_size) {
    (void)in_sizes; (void)n_in; (void)out_size;
    const float* x    = (const float*)d_in[0];
    const float* w    = (const float*)d_in[1];
    const float* bias = (const float*)d_in[2];
    float* out = (float*)d_out;

    reduce_kernel<<<DIM, 256>>>(x, w);                            // launch 1
    finalize_kernel<<<1, 32>>>();                                 // launch 2
    quant_kernel<<<dim3(DIM * DIM / (8 * 256), 2), 256>>>(x, w);  // launch 3
    cudaFuncSetAttribute(gemm_kernel, cudaFuncAttributeMaxDynamicSharedMemorySize, SMEM_TOTAL);
    gemm_kernel<<<GRID_PERSIST, 128, SMEM_TOTAL>>>(bias, out);    // launch 4
}